// round 17
// baseline (speedup 1.0000x reference)
#include <cuda_runtime.h>
#include <cuda_fp16.h>
#include <cstdint>

#define BATCH 512
#define T 128
#define C 384
#define H 6
#define D 64
#define HD 384
#define NQKV 1152

// ---------------- scratch (device globals; no runtime allocation) ----------------
__device__ __align__(256) __half g_xhi[(size_t)BATCH * T * C];
__device__ __align__(256) __half g_wthi[(size_t)NQKV * C];    // [n][k]
__device__ __align__(256) __half g_wpthi[(size_t)HD * C];     // [n][k] = Wp[k][n]
__device__ __align__(256) __half g_atthi[(size_t)BATCH * T * HD];
// q (pre-scaled D^-1/2), k, v single fp16; all [b][h][t][d]
__device__ __align__(256) __half g_q[(size_t)BATCH * H * T * D];
__device__ __align__(256) __half g_k[(size_t)BATCH * H * T * D];
__device__ __align__(256) __half g_v[(size_t)BATCH * H * T * D];

// ---------------- helpers (baseline PTX, compute_103-safe) ----------------
__device__ __forceinline__ uint32_t smem_u32(const void* p) {
    uint32_t a;
    asm("{ .reg .u64 t; cvta.to.shared.u64 t, %1; cvt.u32.u64 %0, t; }" : "=r"(a) : "l"(p));
    return a;
}
__device__ __forceinline__ void ldsm4(uint32_t* r, uint32_t addr) {
    asm volatile("ldmatrix.sync.aligned.m8n8.x4.shared.b16 {%0,%1,%2,%3}, [%4];"
        : "=r"(r[0]), "=r"(r[1]), "=r"(r[2]), "=r"(r[3]) : "r"(addr));
}
__device__ __forceinline__ void ldsm4t(uint32_t* r, uint32_t addr) {
    asm volatile("ldmatrix.sync.aligned.m8n8.x4.trans.shared.b16 {%0,%1,%2,%3}, [%4];"
        : "=r"(r[0]), "=r"(r[1]), "=r"(r[2]), "=r"(r[3]) : "r"(addr));
}
// fp16 MMA, fp32 accum
__device__ __forceinline__ void mma16816f(float* c, const uint32_t* a, const uint32_t* b) {
    asm volatile("mma.sync.aligned.m16n8k16.row.col.f32.f16.f16.f32 "
        "{%0,%1,%2,%3}, {%4,%5,%6,%7}, {%8,%9}, {%0,%1,%2,%3};"
        : "+f"(c[0]), "+f"(c[1]), "+f"(c[2]), "+f"(c[3])
        : "r"(a[0]), "r"(a[1]), "r"(a[2]), "r"(a[3]), "r"(b[0]), "r"(b[1]));
}
__device__ __forceinline__ void cpa16(uint32_t dst, const void* src) {
    asm volatile("cp.async.cg.shared.global [%0], [%1], 16;" :: "r"(dst), "l"(src));
}
#define CPA_COMMIT() asm volatile("cp.async.commit_group;" ::: "memory")
#define CPA_WAIT1()  asm volatile("cp.async.wait_group 1;" ::: "memory")
#define CPA_WAIT0()  asm volatile("cp.async.wait_group 0;" ::: "memory")

__device__ __forceinline__ uint32_t pack_f16x2(float a, float b) {
    __half2 h = __floats2half2_rn(a, b);
    return *(uint32_t*)&h;
}

// =================================================================================
// Fused conversion kernel (R16-proven, MLP=4 x-section).
// =================================================================================
#define NB_X  ((BATCH * T * C / 16) / 256)         // 6144
#define NB_W  ((NQKV * C + 255) / 256)             // 1728
#define NB_WP ((HD * C + 255) / 256)               // 576

__global__ void conv_all_kernel(const float* __restrict__ x,
                                const float* __restrict__ Wq, const float* __restrict__ Wk,
                                const float* __restrict__ Wv, const float* __restrict__ Wp)
{
    const int bid = blockIdx.x;
    if (bid < NB_X) {
        const size_t base = (size_t)bid * (256 * 16) + threadIdx.x * 4;
        float4 v0 = *(const float4*)(x + base);
        float4 v1 = *(const float4*)(x + base + 1024);
        float4 v2 = *(const float4*)(x + base + 2048);
        float4 v3 = *(const float4*)(x + base + 3072);
        *(uint32_t*)(g_xhi + base)          = pack_f16x2(v0.x, v0.y);
        *(uint32_t*)(g_xhi + base + 2)      = pack_f16x2(v0.z, v0.w);
        *(uint32_t*)(g_xhi + base + 1024)   = pack_f16x2(v1.x, v1.y);
        *(uint32_t*)(g_xhi + base + 1026)   = pack_f16x2(v1.z, v1.w);
        *(uint32_t*)(g_xhi + base + 2048)   = pack_f16x2(v2.x, v2.y);
        *(uint32_t*)(g_xhi + base + 2050)   = pack_f16x2(v2.z, v2.w);
        *(uint32_t*)(g_xhi + base + 3072)   = pack_f16x2(v3.x, v3.y);
        *(uint32_t*)(g_xhi + base + 3074)   = pack_f16x2(v3.z, v3.w);
    } else if (bid < NB_X + NB_W) {
        int idx = (bid - NB_X) * 256 + threadIdx.x;   // n*C + k
        if (idx >= NQKV * C) return;
        int n = idx / C, k = idx - n * C;
        int which = n / HD, rem = n - which * HD;
        int h = rem >> 6, d = rem & 63;
        const float* W = (which == 0) ? Wq : (which == 1) ? Wk : Wv;
        g_wthi[idx] = __float2half_rn(W[((size_t)h * C + k) * D + d]);
    } else {
        int idx = (bid - NB_X - NB_W) * 256 + threadIdx.x;   // n*C + k
        if (idx >= HD * C) return;
        int n = idx / C, k = idx - n * C;
        g_wpthi[idx] = __float2half_rn(Wp[(size_t)k * C + n]);
    }
}

// =================================================================================
// A-resident 3-tile GEMM. smem: A resident 6x16KB chunks @0..96K;
// B double buffer 2x16KB @96K,112K. 1 CTA/SM, 128KB smem.
// Each CTA: one batch, 3 consecutive 128-wide n-tiles (18 B-chunks streamed).
// PROJ=false: grid (3, BATCH), blockIdx.x = which; epilogue writes q/k/v fp16.
// PROJ=true : grid (1, BATCH); epilogue adds bias, writes fp32 out.
// =================================================================================
#define G3_SMEM 131072

template <bool PROJ>
__global__ __launch_bounds__(256, 1)
void gemm3(const float* __restrict__ bp, float* __restrict__ out)
{
    extern __shared__ __align__(1024) char sm[];
    const uint32_t smb = smem_u32(sm);
    const int tid = threadIdx.x, wid = tid >> 5, lane = tid & 31;
    const int b = blockIdx.y;
    const int wm = (wid >> 2) * 64;     // 0,64
    const int wn = (wid & 3) * 32;      // 0,32,64,96

    const __half* __restrict__ A = (PROJ ? g_atthi : g_xhi) + (size_t)b * T * C;
    const __half* __restrict__ Wbase = PROJ ? g_wpthi : g_wthi;

    const int l_row = tid >> 3;          // 0..31
    const int l_seg = tid & 7;

    // ---- A resident: 6 chunks of [128 x 64] swizzled, 24 cpa16/thread, 1 group ----
#pragma unroll
    for (int c = 0; c < 6; c++) {
#pragma unroll
        for (int p = 0; p < 4; p++) {
            const int row = l_row + p * 32;
            const uint32_t doff = (uint32_t)(c * 16384 + row * 128 + ((l_seg ^ (row & 7)) << 4));
            cpa16(smb + doff, A + (size_t)row * C + c * 64 + l_seg * 8);
        }
    }
    CPA_COMMIT();

    auto loadB = [&](int idx) {
        const int nt = PROJ ? (idx / 6) : (blockIdx.x * 3 + idx / 6);
        const __half* __restrict__ B = Wbase + (size_t)nt * 128 * C;
        const int c0 = (idx % 6) * 64;
        const uint32_t buf = smb + 98304 + (idx & 1) * 16384;
#pragma unroll
        for (int p = 0; p < 4; p++) {
            const int row = l_row + p * 32;
            const uint32_t doff = (uint32_t)(row * 128 + ((l_seg ^ (row & 7)) << 4));
            cpa16(buf + doff, B + (size_t)row * C + c0 + l_seg * 8);
        }
        CPA_COMMIT();
    };
    loadB(0);
    loadB(1);

    const int rA  = (lane & 7) + ((lane >> 3) & 1) * 8;
    const int khA = lane >> 4;
    const int swA = rA & 7;
    const int rB  = (lane & 7) + (lane >> 4) * 8;
    const int khB = (lane >> 3) & 1;
    const int swB = rB & 7;
    const int qrow = lane >> 2;
    const int qcol = (lane & 3) * 2;

    for (int j = 0; j < 3; j++) {
        float acc[4][4][4];
#pragma unroll
        for (int i = 0; i < 4; i++)
#pragma unroll
            for (int jj = 0; jj < 4; jj++)
#pragma unroll
                for (int e = 0; e < 4; e++) acc[i][jj][e] = 0.f;

        for (int c = 0; c < 6; c++) {
            const int idx = j * 6 + c;
            if (idx < 17) CPA_WAIT1(); else CPA_WAIT0();
            __syncthreads();

            const uint32_t aBase = smb + (uint32_t)(c * 16384 + (wm + rA) * 128);
            const uint32_t bBase = smb + 98304 + (idx & 1) * 16384 + (uint32_t)((wn + rB) * 128);

#pragma unroll
            for (int ks = 0; ks < 4; ks++) {
                const uint32_t aoff = (uint32_t)(((ks * 2 + khA) ^ swA) << 4);
                const uint32_t boff = (uint32_t)(((ks * 2 + khB) ^ swB) << 4);
                uint32_t ah[4][4], bh[2][4];
                ldsm4(ah[0], aBase + aoff);
                ldsm4(bh[0], bBase + boff);
                ldsm4(ah[1], aBase + 2048 + aoff);
                ldsm4(bh[1], bBase + 2048 + boff);
                mma16816f(acc[0][0], ah[0], &bh[0][0]);
                mma16816f(acc[0][1], ah[0], &bh[0][2]);
                ldsm4(ah[2], aBase + 4096 + aoff);
                mma16816f(acc[0][2], ah[0], &bh[1][0]);
                mma16816f(acc[0][3], ah[0], &bh[1][2]);
                ldsm4(ah[3], aBase + 6144 + aoff);
                mma16816f(acc[1][0], ah[1], &bh[0][0]);
                mma16816f(acc[1][1], ah[1], &bh[0][2]);
                mma16816f(acc[1][2], ah[1], &bh[1][0]);
                mma16816f(acc[1][3], ah[1], &bh[1][2]);
#pragma unroll
                for (int mf = 2; mf < 4; mf++) {
                    mma16816f(acc[mf][0], ah[mf], &bh[0][0]);
                    mma16816f(acc[mf][1], ah[mf], &bh[0][2]);
                    mma16816f(acc[mf][2], ah[mf], &bh[1][0]);
                    mma16816f(acc[mf][3], ah[mf], &bh[1][2]);
                }
            }
            __syncthreads();
            if (idx + 2 < 18) loadB(idx + 2);
        }

        // ---------------- epilogue for tile j ----------------
        if (PROJ) {
            const int n0 = j * 128;
#pragma unroll
            for (int mf = 0; mf < 4; mf++) {
#pragma unroll
                for (int nf = 0; nf < 4; nf++) {
                    const int row = wm + mf * 16 + qrow;
                    const int col = n0 + wn + nf * 8 + qcol;
                    const float2 bb = *(const float2*)(bp + col);
                    float* p0 = out + ((size_t)b * T + row) * HD + col;
                    float* p1 = out + ((size_t)b * T + row + 8) * HD + col;
                    *(float2*)p0 = make_float2(acc[mf][nf][0] + bb.x, acc[mf][nf][1] + bb.y);
                    *(float2*)p1 = make_float2(acc[mf][nf][2] + bb.x, acc[mf][nf][3] + bb.y);
                }
            }
        } else {
            const int which = blockIdx.x;
            __half* dst = (which == 0) ? g_q : (which == 1) ? g_k : g_v;
            const float scale = (which == 0) ? 0.125f : 1.0f;
            const int rem0 = j * 128;
#pragma unroll
            for (int mf = 0; mf < 4; mf++) {
#pragma unroll
                for (int nf = 0; nf < 4; nf++) {
                    const int row = wm + mf * 16 + qrow;
                    const int rem = rem0 + wn + nf * 8 + qcol;
                    const int hh = rem >> 6, dd = rem & 63;
                    const size_t o0 = (((size_t)(b * H + hh) * T) + row) * D + dd;
                    *(uint32_t*)(dst + o0) =
                        pack_f16x2(acc[mf][nf][0] * scale, acc[mf][nf][1] * scale);
                    *(uint32_t*)(dst + o0 + 8 * D) =
                        pack_f16x2(acc[mf][nf][2] * scale, acc[mf][nf][3] * scale);
                }
            }
        }
    }
}

// =================================================================================
// MMA attention per (b, h) (R16-proven): Q/K/V/P single fp16, fp32 accum,
// V as a second overlapped cp.async group. 48KB smem; 2 CTAs/SM.
// =================================================================================
#define ATTN_SMEM 49152

__global__ __launch_bounds__(256, 2)
void attn_mma()
{
    extern __shared__ __align__(1024) char sm[];
    const uint32_t smb = smem_u32(sm);
    const int tid = threadIdx.x, w = tid >> 5, lane = tid & 31;
    const int b = blockIdx.x, h = blockIdx.y;
    const int rb = (w < 4) ? w : (11 - w);

    const size_t blk = (size_t)(b * H + h) * (T * D);
    {
        const int seg = tid & 7;
#pragma unroll
        for (int p = 0; p < 4; p++) {
            const int row = (tid + p * 256) >> 3;
            const uint32_t doff = (uint32_t)(row * 128 + ((seg ^ (row & 7)) << 4));
            const size_t soff = blk + (size_t)row * D + seg * 8;
            cpa16(smb + doff,         g_q + soff);
            cpa16(smb + 16384 + doff, g_k + soff);
        }
        CPA_COMMIT();
#pragma unroll
        for (int p = 0; p < 4; p++) {
            const int row = (tid + p * 256) >> 3;
            const uint32_t doff = (uint32_t)(row * 128 + ((seg ^ (row & 7)) << 4));
            const size_t soff = blk + (size_t)row * D + seg * 8;
            cpa16(smb + 32768 + doff, g_v + soff);
        }
        CPA_COMMIT();
    }
    CPA_WAIT1();
    __syncthreads();

    const int rA  = (lane & 7) + ((lane >> 3) & 1) * 8;
    const int khA = lane >> 4;
    const int swA = rA & 7;
    const int rB  = (lane & 7) + (lane >> 4) * 8;
    const int khB = (lane >> 3) & 1;
    const int swB = rB & 7;

    const uint32_t aQ = smb + (uint32_t)((rb * 16 + rA) * 128);

    float S[16][4];
#pragma unroll
    for (int i = 0; i < 16; i++)
#pragma unroll
        for (int e = 0; e < 4; e++) S[i][e] = 0.f;

#pragma unroll
    for (int ks = 0; ks < 4; ks++) {
        uint32_t qh[4];
        const uint32_t aoff = (uint32_t)(((ks * 2 + khA) ^ swA) << 4);
        ldsm4(qh, aQ + aoff);
        const uint32_t boff = (uint32_t)(((ks * 2 + khB) ^ swB) << 4);
#pragma unroll
        for (int g = 0; g < 8; g += 2) {
            if (g > rb) break;
            uint32_t kh0[4];
            const uint32_t bb0 = smb + 16384 + (uint32_t)((g * 16 + rB) * 128);
            ldsm4(kh0, bb0 + boff);
            const bool g1ok = (g + 1) <= rb;
            uint32_t kh1[4];
            if (g1ok) {
                const uint32_t bb1 = smb + 16384 + (uint32_t)(((g + 1) * 16 + rB) * 128);
                ldsm4(kh1, bb1 + boff);
            }
            mma16816f(S[2 * g],     qh, &kh0[0]);
            mma16816f(S[2 * g + 1], qh, &kh0[2]);
            if (g1ok) {
                mma16816f(S[2 * g + 2], qh, &kh1[0]);
                mma16816f(S[2 * g + 3], qh, &kh1[2]);
            }
        }
    }

    const int row0 = rb * 16 + (lane >> 2);
    const int row1 = row0 + 8;
    const int colb = 2 * (lane & 3);
    float sum0 = 0.f, sum1 = 0.f;
#pragma unroll
    for (int nf = 0; nf < 16; nf++) {
        if (nf > 2 * rb + 1) break;
        const int c0 = nf * 8 + colb, c1 = c0 + 1;
        float e00 = (c0 <= row0) ? __expf(S[nf][0]) : 0.f;
        float e01 = (c1 <= row0) ? __expf(S[nf][1]) : 0.f;
        float e10 = (c0 <= row1) ? __expf(S[nf][2]) : 0.f;
        float e11 = (c1 <= row1) ? __expf(S[nf][3]) : 0.f;
        S[nf][0] = e00; S[nf][1] = e01; S[nf][2] = e10; S[nf][3] = e11;
        sum0 += e00 + e01;
        sum1 += e10 + e11;
    }
    sum0 += __shfl_xor_sync(0xFFFFFFFFu, sum0, 1);
    sum0 += __shfl_xor_sync(0xFFFFFFFFu, sum0, 2);
    sum1 += __shfl_xor_sync(0xFFFFFFFFu, sum1, 1);
    sum1 += __shfl_xor_sync(0xFFFFFFFFu, sum1, 2);
    const float inv0 = 1.0f / sum0;
    const float inv1 = 1.0f / sum1;

    CPA_WAIT0();
    __syncthreads();

    float O[8][4];
#pragma unroll
    for (int i = 0; i < 8; i++)
#pragma unroll
        for (int e = 0; e < 4; e++) O[i][e] = 0.f;

    const int mT = lane >> 3;
    const int rT = lane & 7;

#pragma unroll
    for (int ks = 0; ks < 8; ks++) {
        if (ks > rb) break;
        const int srow = ks * 16 + (mT & 1) * 8 + rT;
        const uint32_t rowOff = (uint32_t)(srow * 128);
        uint32_t vh[4][4];
        {
            const int dseg0 = (mT >> 1);
            const uint32_t a0 = rowOff + (uint32_t)(((dseg0 ^ (srow & 7)) << 4));
            ldsm4t(vh[0], smb + 32768 + a0);
        }
        uint32_t phi[4];
        phi[0] = pack_f16x2(S[2 * ks][0],     S[2 * ks][1]);
        phi[1] = pack_f16x2(S[2 * ks][2],     S[2 * ks][3]);
        phi[2] = pack_f16x2(S[2 * ks + 1][0], S[2 * ks + 1][1]);
        phi[3] = pack_f16x2(S[2 * ks + 1][2], S[2 * ks + 1][3]);
#pragma unroll
        for (int g = 1; g < 4; g++) {
            const int dseg = g * 2 + (mT >> 1);
            const uint32_t addr = rowOff + (uint32_t)(((dseg ^ (srow & 7)) << 4));
            ldsm4t(vh[g], smb + 32768 + addr);
            mma16816f(O[2 * (g - 1)],     phi, &vh[g - 1][0]);
            mma16816f(O[2 * (g - 1) + 1], phi, &vh[g - 1][2]);
        }
        mma16816f(O[6], phi, &vh[3][0]);
        mma16816f(O[7], phi, &vh[3][2]);
    }

    const size_t obase = (size_t)b * T * HD + h * D;
#pragma unroll
    for (int nf = 0; nf < 8; nf++) {
        const int d0 = nf * 8 + colb;
        *(uint32_t*)(g_atthi + obase + (size_t)row0 * HD + d0) =
            pack_f16x2(O[nf][0] * inv0, O[nf][1] * inv0);
        *(uint32_t*)(g_atthi + obase + (size_t)row1 * HD + d0) =
            pack_f16x2(O[nf][2] * inv1, O[nf][3] * inv1);
    }
}

// =================================================================================
extern "C" void kernel_launch(void* const* d_in, const int* in_sizes, int n_in,
                              void* d_out, int out_size)
{
    (void)in_sizes; (void)n_in; (void)out_size;
    const float* x  = (const float*)d_in[0];
    const float* Wq = (const float*)d_in[1];
    const float* Wk = (const float*)d_in[2];
    const float* Wv = (const float*)d_in[3];
    const float* Wp = (const float*)d_in[4];
    const float* bp = (const float*)d_in[5];
    float* out = (float*)d_out;

    cudaFuncSetAttribute(gemm3<false>, cudaFuncAttributeMaxDynamicSharedMemorySize, G3_SMEM);
    cudaFuncSetAttribute(gemm3<true>,  cudaFuncAttributeMaxDynamicSharedMemorySize, G3_SMEM);
    cudaFuncSetAttribute(attn_mma,     cudaFuncAttributeMaxDynamicSharedMemorySize, ATTN_SMEM);

    conv_all_kernel<<<NB_X + NB_W + NB_WP, 256>>>(x, Wq, Wk, Wv, Wp);

    gemm3<false><<<dim3(3, BATCH), 256, G3_SMEM>>>(nullptr, nullptr);
    attn_mma<<<dim3(BATCH, H), 256, ATTN_SMEM>>>();
    gemm3<true><<<dim3(1, BATCH), 256, G3_SMEM>>>(bp, out);
}